// round 13
// baseline (speedup 1.0000x reference)
#include <cuda_runtime.h>
#include <cuda_fp16.h>
#include <cstdint>

// out[b,m,n] = round(alpha * sum_k A[b,m,k]*B[b,n,k]); B=64, M=N=1024, K=128.
// Harness facts: inputs materialized int32, output compared float32,
// ptxas = sm_103 (no tcgen05). HMMA f16 path (exact for int8 data).
//
// Round-13: GEMM epilogue rewritten for full-line stores. Rounds 11/12 both
// pinned at stores = 268MB / 83us = 3.22 TB/s with 32B-sector-fragmented
// STG.64; now each warp transposes its 64x32 f32 block through padded smem
// and issues STG.128 covering complete 128B lines.

static constexpr int M_DIM = 1024;
static constexpr int N_DIM = 1024;
static constexpr int K_DIM = 128;
static constexpr int BATCH = 64;
static constexpr int TILES = 8 * 8 * BATCH;   // 4096
static constexpr int GRID  = 304;             // 2 CTAs/SM on 152 SMs
static constexpr float ALPHA_CONST = 0.0078125f;

static constexpr uint32_t SLOT_BYTES = 16384;   // A 8KB @0, B 8KB @8192
static constexpr uint32_t B_OFF      = 8192;
static constexpr uint32_t STG_OFF    = 65536;   // staging region after 4 slots
static constexpr int      STG_STRIDE = 40;      // floats per staged row (16B-aligned, padded)
static constexpr uint32_t SMEM_TOTAL = STG_OFF + 8 * 16 * STG_STRIDE * 4;  // 86016

__device__ __half g_ah[(size_t)BATCH * M_DIM * K_DIM];
__device__ __half g_bh[(size_t)BATCH * N_DIM * K_DIM];

__device__ __forceinline__ uint32_t h2pack(int x, int y) {
    __half2 h = __halves2half2(__int2half_rn(x), __int2half_rn(y));
    return *reinterpret_cast<uint32_t*>(&h);
}

// ---------------- kernel 1: int32 -> f16 pack ----------------
__global__ __launch_bounds__(256)
void pack_kernel(const int4* __restrict__ A, const int4* __restrict__ B) {
    size_t t = (size_t)blockIdx.x * 256 + threadIdx.x;   // one 16-value group

    int4 a[4], b[4];
    #pragma unroll
    for (int i = 0; i < 4; i++) { a[i] = A[t * 4 + i]; b[i] = B[t * 4 + i]; }

    uint4 ha0, ha1, hb0, hb1;
    ha0.x = h2pack(a[0].x, a[0].y); ha0.y = h2pack(a[0].z, a[0].w);
    ha0.z = h2pack(a[1].x, a[1].y); ha0.w = h2pack(a[1].z, a[1].w);
    ha1.x = h2pack(a[2].x, a[2].y); ha1.y = h2pack(a[2].z, a[2].w);
    ha1.z = h2pack(a[3].x, a[3].y); ha1.w = h2pack(a[3].z, a[3].w);
    hb0.x = h2pack(b[0].x, b[0].y); hb0.y = h2pack(b[0].z, b[0].w);
    hb0.z = h2pack(b[1].x, b[1].y); hb0.w = h2pack(b[1].z, b[1].w);
    hb1.x = h2pack(b[2].x, b[2].y); hb1.y = h2pack(b[2].z, b[2].w);
    hb1.z = h2pack(b[3].x, b[3].y); hb1.w = h2pack(b[3].z, b[3].w);
    reinterpret_cast<uint4*>(g_ah)[t * 2 + 0] = ha0;
    reinterpret_cast<uint4*>(g_ah)[t * 2 + 1] = ha1;
    reinterpret_cast<uint4*>(g_bh)[t * 2 + 0] = hb0;
    reinterpret_cast<uint4*>(g_bh)[t * 2 + 1] = hb1;
}

__device__ __forceinline__ void cp16(uint32_t dst, const void* src) {
    asm volatile("cp.async.cg.shared.global [%0], [%1], 16;"
                 :: "r"(dst), "l"(src) : "memory");
}

// ---------------- kernel 2: pipelined persistent HMMA GEMM ----------------
__global__ __launch_bounds__(256, 2)
void gemm_hmma_kernel(const float* __restrict__ alpha_p,
                      float* __restrict__ out)
{
    extern __shared__ int8_t smem[];   // 4 slots x 16KB + 20KB staging

    const int tid  = threadIdx.x;
    const int warp = tid >> 5;
    const int lane = tid & 31;
    const int bid  = blockIdx.x;

    const float alpha = alpha_p ? *alpha_p : ALPHA_CONST;
    const uint32_t smemS = (uint32_t)__cvta_generic_to_shared(smem);

    const int mBase = (warp >> 2) * 64;   // warp row: 0 or 64
    const int nBase = (warp & 3) * 32;    // warp col: 0,32,64,96
    const int sub = lane >> 3;
    const int r8 = lane & 7;
    const int ld_row_off = ((sub & 1) << 3) + r8;
    const int ld_chunk   = sub >> 1;      // 0/1: which 16B within a k16 step
    const int g  = lane >> 2;
    const int tq = lane & 3;

    float* stg = reinterpret_cast<float*>(smem + STG_OFF)
               + warp * 16 * STG_STRIDE;   // 16 rows x 40 floats per warp

    auto load_stage = [&](int gs) {
        const int t = bid + (gs >> 2) * GRID;
        if (t < TILES) {
            const int kc = gs & 3;
            const int bn = t & 7, bm = (t >> 3) & 7, bz = t >> 6;
            const int8_t* gA = reinterpret_cast<const int8_t*>(g_ah)
                + ((size_t)bz * M_DIM + (size_t)bm * 128) * (K_DIM * 2);
            const int8_t* gB = reinterpret_cast<const int8_t*>(g_bh)
                + ((size_t)bz * N_DIM + (size_t)bn * 128) * (K_DIM * 2);
            const uint32_t slot = smemS + (uint32_t)(gs & 3) * SLOT_BYTES;
            #pragma unroll
            for (int i = 0; i < 2; i++) {
                int idx = tid + i * 256;          // 0..511: row*4 + chunk
                int row = idx >> 2;
                int c   = idx & 3;
                uint32_t soff = (uint32_t)row * 64
                              + (uint32_t)((c ^ ((row >> 1) & 3)) << 4);
                const size_t goff = (size_t)row * 256 + (size_t)kc * 64 + (size_t)c * 16;
                cp16(slot + soff,         gA + goff);
                cp16(slot + B_OFF + soff, gB + goff);
            }
        }
        asm volatile("cp.async.commit_group;" ::: "memory");
    };

    const int ntiles = (TILES - bid + GRID - 1) / GRID;
    const int total_stages = ntiles * 4;

    load_stage(0);
    load_stage(1);
    load_stage(2);

    float acc[4][4][4];

    for (int gs = 0; gs < total_stages; gs++) {
        asm volatile("cp.async.wait_group 2;" ::: "memory");
        __syncthreads();   // stage data visible; prior slot reads finished

        if ((gs & 3) == 0) {
            #pragma unroll
            for (int mi = 0; mi < 4; mi++)
                #pragma unroll
                for (int ni = 0; ni < 4; ni++)
                    #pragma unroll
                    for (int r = 0; r < 4; r++)
                        acc[mi][ni][r] = 0.0f;
        }

        const uint32_t slot = smemS + (uint32_t)(gs & 3) * SLOT_BYTES;

        #pragma unroll
        for (int kk2 = 0; kk2 < 2; kk2++) {       // 2 x k16 per stage
            const int c = kk2 * 2 + ld_chunk;

            uint32_t a[4][4];
            #pragma unroll
            for (int mi = 0; mi < 4; mi++) {
                int row = mBase + mi * 16 + ld_row_off;
                uint32_t addr = slot + (uint32_t)row * 64
                              + (uint32_t)((c ^ ((row >> 1) & 3)) << 4);
                asm volatile(
                    "ldmatrix.sync.aligned.m8n8.x4.shared.b16 {%0,%1,%2,%3}, [%4];"
                    : "=r"(a[mi][0]), "=r"(a[mi][1]), "=r"(a[mi][2]), "=r"(a[mi][3])
                    : "r"(addr));
            }
            uint32_t b[2][4];
            #pragma unroll
            for (int nj = 0; nj < 2; nj++) {
                int row = nBase + nj * 16 + ld_row_off;
                uint32_t addr = slot + B_OFF + (uint32_t)row * 64
                              + (uint32_t)((c ^ ((row >> 1) & 3)) << 4);
                asm volatile(
                    "ldmatrix.sync.aligned.m8n8.x4.shared.b16 {%0,%1,%2,%3}, [%4];"
                    : "=r"(b[nj][0]), "=r"(b[nj][1]), "=r"(b[nj][2]), "=r"(b[nj][3])
                    : "r"(addr));
            }
            #pragma unroll
            for (int mi = 0; mi < 4; mi++) {
                #pragma unroll
                for (int ni = 0; ni < 4; ni++) {
                    const int nj = ni >> 1;
                    const int up = ni & 1;
                    asm volatile(
                        "mma.sync.aligned.m16n8k16.row.col.f32.f16.f16.f32 "
                        "{%0,%1,%2,%3}, {%4,%5,%6,%7}, {%8,%9}, {%0,%1,%2,%3};"
                        : "+f"(acc[mi][ni][0]), "+f"(acc[mi][ni][1]),
                          "+f"(acc[mi][ni][2]), "+f"(acc[mi][ni][3])
                        : "r"(a[mi][0]), "r"(a[mi][1]), "r"(a[mi][2]), "r"(a[mi][3]),
                          "r"(b[nj][up]), "r"(b[nj][up + 2]));
                }
            }
        }

        load_stage(gs + 3);   // refill pipeline (slot (gs+3)&3 is free)

        if ((gs & 3) == 3) {
            const int t = bid + (gs >> 2) * GRID;
            const int bn = t & 7, bm = (t >> 3) & 7, bz = t >> 6;
            float* gOut = out + ((size_t)bz * M_DIM + (size_t)bm * 128) * N_DIM
                              + (size_t)bn * 128;

            // Full-line epilogue: per 16-row group, transpose through padded
            // smem, then STG.128 covering complete 128B lines.
            #pragma unroll
            for (int mi = 0; mi < 4; mi++) {
                #pragma unroll
                for (int ni = 0; ni < 4; ni++) {
                    const int cl = ni * 8 + tq * 2;
                    float2 v0, v1;
                    v0.x = rintf(acc[mi][ni][0] * alpha);
                    v0.y = rintf(acc[mi][ni][1] * alpha);
                    v1.x = rintf(acc[mi][ni][2] * alpha);
                    v1.y = rintf(acc[mi][ni][3] * alpha);
                    *reinterpret_cast<float2*>(stg + g * STG_STRIDE + cl)       = v0;
                    *reinterpret_cast<float2*>(stg + (g + 8) * STG_STRIDE + cl) = v1;
                }
                __syncwarp();
                #pragma unroll
                for (int p = 0; p < 4; p++) {
                    const int rl = p * 4 + (lane >> 3);          // 0..15
                    const int c4 = (lane & 7) * 4;               // 0..28
                    float4 v = *reinterpret_cast<float4*>(stg + rl * STG_STRIDE + c4);
                    *reinterpret_cast<float4*>(
                        gOut + (size_t)(mBase + mi * 16 + rl) * N_DIM + nBase + c4) = v;
                }
                __syncwarp();
            }
        }
    }
}

extern "C" void kernel_launch(void* const* d_in, const int* in_sizes, int n_in,
                              void* d_out, int out_size) {
    int i_alpha = -1;
    for (int i = 0; i < n_in; i++)
        if (in_sizes[i] == 1) { i_alpha = i; break; }
    int big[2] = {-1, -1};
    int nb = 0;
    for (int i = 0; i < n_in && nb < 2; i++)
        if (i != i_alpha) big[nb++] = i;
    if (nb < 2) return;

    const int4*  a     = (const int4*)d_in[big[0]];
    const int4*  b     = (const int4*)d_in[big[1]];
    const float* alpha = (i_alpha >= 0) ? (const float*)d_in[i_alpha] : nullptr;
    float*       out   = (float*)d_out;

    static bool attr_set = false;
    if (!attr_set) {
        cudaFuncSetAttribute(gemm_hmma_kernel,
                             cudaFuncAttributeMaxDynamicSharedMemorySize, SMEM_TOTAL);
        attr_set = true;
    }

    pack_kernel<<<2048, 256>>>(a, b);                        // int32 -> f16
    gemm_hmma_kernel<<<GRID, 256, SMEM_TOTAL>>>(alpha, out); // pipelined GEMM
}

// round 14
// speedup vs baseline: 1.0185x; 1.0185x over previous
#include <cuda_runtime.h>
#include <cuda_fp16.h>
#include <cstdint>

// out[b,m,n] = round(alpha * sum_k A[b,m,k]*B[b,n,k]); B=64, M=N=1024, K=128.
// Inputs materialized int32, output f32, ptxas = sm_103 (no tcgen05).
//
// Round-14: break SM-wide phase lockstep. 4 CTAs/SM x 128 threads, CTA tile
// 128x64 (warp tile 64x32 = verified geometry). Independent CTAs drift so
// LDS bursts of one overlap HMMA bursts of another. Same 4-slot cp.async
// k32-stage pipeline (12KB/stage).

static constexpr int M_DIM = 1024;
static constexpr int N_DIM = 1024;
static constexpr int K_DIM = 128;
static constexpr int BATCH = 64;
static constexpr int TILES = 8 * 16 * BATCH;  // 8192 (128x64 tiles)
static constexpr int GRID  = 608;             // 4 CTAs/SM on 152 SMs
static constexpr float ALPHA_CONST = 0.0078125f;

static constexpr uint32_t SLOT_BYTES = 12288;   // A 8KB @0, B 4KB @8192
static constexpr uint32_t B_OFF      = 8192;
static constexpr uint32_t SMEM_TOTAL = 4 * SLOT_BYTES;   // 49152

__device__ __half g_ah[(size_t)BATCH * M_DIM * K_DIM];
__device__ __half g_bh[(size_t)BATCH * N_DIM * K_DIM];

__device__ __forceinline__ uint32_t h2pack(int x, int y) {
    __half2 h = __halves2half2(__int2half_rn(x), __int2half_rn(y));
    return *reinterpret_cast<uint32_t*>(&h);
}

// ---------------- kernel 1: int32 -> f16 pack ----------------
__global__ __launch_bounds__(256)
void pack_kernel(const int4* __restrict__ A, const int4* __restrict__ B) {
    size_t t = (size_t)blockIdx.x * 256 + threadIdx.x;   // one 16-value group

    int4 a[4], b[4];
    #pragma unroll
    for (int i = 0; i < 4; i++) { a[i] = A[t * 4 + i]; b[i] = B[t * 4 + i]; }

    uint4 ha0, ha1, hb0, hb1;
    ha0.x = h2pack(a[0].x, a[0].y); ha0.y = h2pack(a[0].z, a[0].w);
    ha0.z = h2pack(a[1].x, a[1].y); ha0.w = h2pack(a[1].z, a[1].w);
    ha1.x = h2pack(a[2].x, a[2].y); ha1.y = h2pack(a[2].z, a[2].w);
    ha1.z = h2pack(a[3].x, a[3].y); ha1.w = h2pack(a[3].z, a[3].w);
    hb0.x = h2pack(b[0].x, b[0].y); hb0.y = h2pack(b[0].z, b[0].w);
    hb0.z = h2pack(b[1].x, b[1].y); hb0.w = h2pack(b[1].z, b[1].w);
    hb1.x = h2pack(b[2].x, b[2].y); hb1.y = h2pack(b[2].z, b[2].w);
    hb1.z = h2pack(b[3].x, b[3].y); hb1.w = h2pack(b[3].z, b[3].w);
    reinterpret_cast<uint4*>(g_ah)[t * 2 + 0] = ha0;
    reinterpret_cast<uint4*>(g_ah)[t * 2 + 1] = ha1;
    reinterpret_cast<uint4*>(g_bh)[t * 2 + 0] = hb0;
    reinterpret_cast<uint4*>(g_bh)[t * 2 + 1] = hb1;
}

__device__ __forceinline__ void cp16(uint32_t dst, const void* src) {
    asm volatile("cp.async.cg.shared.global [%0], [%1], 16;"
                 :: "r"(dst), "l"(src) : "memory");
}

// ---------------- kernel 2: 4-CTA/SM pipelined HMMA GEMM ----------------
// Tile map: bn = t & 15 (64-wide), bm = (t>>4) & 7 (128-tall), bz = t >> 7.
__global__ __launch_bounds__(128, 4)
void gemm_hmma_kernel(const float* __restrict__ alpha_p,
                      float* __restrict__ out)
{
    extern __shared__ int8_t smem[];   // 4 slots x 12KB

    const int tid  = threadIdx.x;
    const int warp = tid >> 5;
    const int lane = tid & 31;
    const int bid  = blockIdx.x;

    const float alpha = alpha_p ? *alpha_p : ALPHA_CONST;
    const uint32_t smemS = (uint32_t)__cvta_generic_to_shared(smem);

    const int mBase = (warp >> 1) * 64;   // warp row: 0 or 64
    const int nBase = (warp & 1) * 32;    // warp col: 0 or 32
    const int sub = lane >> 3;
    const int r8 = lane & 7;
    const int ld_row_off = ((sub & 1) << 3) + r8;
    const int ld_chunk   = sub >> 1;      // 0/1: which 16B within a k16 step
    const int g  = lane >> 2;
    const int tq = lane & 3;

    // Load stage gs: tile = bid + (gs>>2)*GRID, k-chunk kc = gs&3.
    // A slice: 128 rows x 64B (512 chunks); B slice: 64 rows x 64B (256).
    // Always commits a group (uniform wait_group counting).
    auto load_stage = [&](int gs) {
        const int t = bid + (gs >> 2) * GRID;
        if (t < TILES) {
            const int kc = gs & 3;
            const int bn = t & 15, bm = (t >> 4) & 7, bz = t >> 7;
            const int8_t* gA = reinterpret_cast<const int8_t*>(g_ah)
                + ((size_t)bz * M_DIM + (size_t)bm * 128) * (K_DIM * 2);
            const int8_t* gB = reinterpret_cast<const int8_t*>(g_bh)
                + ((size_t)bz * N_DIM + (size_t)bn * 64) * (K_DIM * 2);
            const uint32_t slot = smemS + (uint32_t)(gs & 3) * SLOT_BYTES;
            #pragma unroll
            for (int i = 0; i < 6; i++) {
                int idx = tid + i * 128;          // 0..767
                if (idx < 512) {                  // A: row*4 + chunk
                    int row = idx >> 2;
                    int c   = idx & 3;
                    uint32_t soff = (uint32_t)row * 64
                                  + (uint32_t)((c ^ ((row >> 1) & 3)) << 4);
                    cp16(slot + soff,
                         gA + (size_t)row * 256 + (size_t)kc * 64 + (size_t)c * 16);
                } else {                           // B
                    int j   = idx - 512;
                    int row = j >> 2;
                    int c   = j & 3;
                    uint32_t soff = (uint32_t)row * 64
                                  + (uint32_t)((c ^ ((row >> 1) & 3)) << 4);
                    cp16(slot + B_OFF + soff,
                         gB + (size_t)row * 256 + (size_t)kc * 64 + (size_t)c * 16);
                }
            }
        }
        asm volatile("cp.async.commit_group;" ::: "memory");
    };

    const int ntiles = (TILES - bid + GRID - 1) / GRID;
    const int total_stages = ntiles * 4;

    load_stage(0);
    load_stage(1);
    load_stage(2);

    float acc[4][4][4];

    for (int gs = 0; gs < total_stages; gs++) {
        asm volatile("cp.async.wait_group 2;" ::: "memory");
        __syncthreads();   // stage data visible; prior slot reads finished

        if ((gs & 3) == 0) {
            #pragma unroll
            for (int mi = 0; mi < 4; mi++)
                #pragma unroll
                for (int ni = 0; ni < 4; ni++)
                    #pragma unroll
                    for (int r = 0; r < 4; r++)
                        acc[mi][ni][r] = 0.0f;
        }

        const uint32_t slot = smemS + (uint32_t)(gs & 3) * SLOT_BYTES;

        #pragma unroll
        for (int kk2 = 0; kk2 < 2; kk2++) {       // 2 x k16 per stage
            const int c = kk2 * 2 + ld_chunk;

            uint32_t a[4][4];
            #pragma unroll
            for (int mi = 0; mi < 4; mi++) {
                int row = mBase + mi * 16 + ld_row_off;
                uint32_t addr = slot + (uint32_t)row * 64
                              + (uint32_t)((c ^ ((row >> 1) & 3)) << 4);
                asm volatile(
                    "ldmatrix.sync.aligned.m8n8.x4.shared.b16 {%0,%1,%2,%3}, [%4];"
                    : "=r"(a[mi][0]), "=r"(a[mi][1]), "=r"(a[mi][2]), "=r"(a[mi][3])
                    : "r"(addr));
            }
            uint32_t b[2][4];
            #pragma unroll
            for (int nj = 0; nj < 2; nj++) {
                int row = nBase + nj * 16 + ld_row_off;
                uint32_t addr = slot + B_OFF + (uint32_t)row * 64
                              + (uint32_t)((c ^ ((row >> 1) & 3)) << 4);
                asm volatile(
                    "ldmatrix.sync.aligned.m8n8.x4.shared.b16 {%0,%1,%2,%3}, [%4];"
                    : "=r"(b[nj][0]), "=r"(b[nj][1]), "=r"(b[nj][2]), "=r"(b[nj][3])
                    : "r"(addr));
            }
            #pragma unroll
            for (int mi = 0; mi < 4; mi++) {
                #pragma unroll
                for (int ni = 0; ni < 4; ni++) {
                    const int nj = ni >> 1;
                    const int up = ni & 1;
                    asm volatile(
                        "mma.sync.aligned.m16n8k16.row.col.f32.f16.f16.f32 "
                        "{%0,%1,%2,%3}, {%4,%5,%6,%7}, {%8,%9}, {%0,%1,%2,%3};"
                        : "+f"(acc[mi][ni][0]), "+f"(acc[mi][ni][1]),
                          "+f"(acc[mi][ni][2]), "+f"(acc[mi][ni][3])
                        : "r"(a[mi][0]), "r"(a[mi][1]), "r"(a[mi][2]), "r"(a[mi][3]),
                          "r"(b[nj][up]), "r"(b[nj][up + 2]));
                }
            }
        }

        load_stage(gs + 3);   // refill pipeline (slot (gs+3)&3 is free)

        if ((gs & 3) == 3) {
            const int t = bid + (gs >> 2) * GRID;
            const int bn = t & 15, bm = (t >> 4) & 7, bz = t >> 7;
            float* gOut = out + ((size_t)bz * M_DIM + (size_t)bm * 128) * N_DIM
                              + (size_t)bn * 64;
            #pragma unroll
            for (int mi = 0; mi < 4; mi++) {
                #pragma unroll
                for (int ni = 0; ni < 4; ni++) {
                    int r0 = mBase + mi * 16 + g;
                    int c2 = nBase + ni * 8 + tq * 2;
                    float2 v0, v1;
                    v0.x = rintf(acc[mi][ni][0] * alpha);
                    v0.y = rintf(acc[mi][ni][1] * alpha);
                    v1.x = rintf(acc[mi][ni][2] * alpha);
                    v1.y = rintf(acc[mi][ni][3] * alpha);
                    *reinterpret_cast<float2*>(gOut + (size_t)r0 * N_DIM + c2)       = v0;
                    *reinterpret_cast<float2*>(gOut + (size_t)(r0 + 8) * N_DIM + c2) = v1;
                }
            }
        }
    }
}

extern "C" void kernel_launch(void* const* d_in, const int* in_sizes, int n_in,
                              void* d_out, int out_size) {
    int i_alpha = -1;
    for (int i = 0; i < n_in; i++)
        if (in_sizes[i] == 1) { i_alpha = i; break; }
    int big[2] = {-1, -1};
    int nb = 0;
    for (int i = 0; i < n_in && nb < 2; i++)
        if (i != i_alpha) big[nb++] = i;
    if (nb < 2) return;

    const int4*  a     = (const int4*)d_in[big[0]];
    const int4*  b     = (const int4*)d_in[big[1]];
    const float* alpha = (i_alpha >= 0) ? (const float*)d_in[i_alpha] : nullptr;
    float*       out   = (float*)d_out;

    static bool attr_set = false;
    if (!attr_set) {
        cudaFuncSetAttribute(gemm_hmma_kernel,
                             cudaFuncAttributeMaxDynamicSharedMemorySize, SMEM_TOTAL);
        attr_set = true;
    }

    pack_kernel<<<2048, 256>>>(a, b);                        // int32 -> f16
    gemm_hmma_kernel<<<GRID, 128, SMEM_TOTAL>>>(alpha, out); // 4-CTA/SM GEMM
}